// round 2
// baseline (speedup 1.0000x reference)
#include <cuda_runtime.h>
#include <cstdint>
#include <cstddef>

#define D0 32
#define D1 128
#define D2 64
#define NG 16
#define NEG_SLOPE 0.01f
#define EPSV 1e-5f
#define MAXN 1000000

// ---------------- scratch (static device globals; no runtime allocation) ----
__device__ float g_h1[(size_t)MAXN * D1];   // 512 MB: pre-norm layer-1 activations
__device__ float g_h2[(size_t)MAXN * D2];   // 256 MB: pre-norm layer-2 activations
__device__ float g_sum1[NG * D1], g_sq1[NG * D1];
__device__ float g_sum2[NG * D2], g_sq2[NG * D2];
__device__ float g_scale1[NG * D1], g_shift1[NG * D1];
__device__ float g_scale2[NG * D2], g_shift2[NG * D2];
__device__ float g_cntf[NG];

// ---------------- init: out = -inf, stats = 0 -------------------------------
__global__ void k_init(float* __restrict__ out, int out_n) {
    int i = blockIdx.x * blockDim.x + threadIdx.x;
    if (i < out_n) out[i] = __int_as_float(0xFF800000);  // -inf
    if (i < NG * D1) { g_sum1[i] = 0.f; g_sq1[i] = 0.f; }
    if (i < NG * D2) { g_sum2[i] = 0.f; g_sq2[i] = 0.f; }
}

// ---------------- k1: h1 = x @ W1^T + b1, accumulate per-graph stats --------
// blockDim = 128 (one thread per output channel), 256 nodes per block.
__global__ void __launch_bounds__(128) k1(
    const float* __restrict__ x, const float* __restrict__ W1,
    const float* __restrict__ b1, const int* __restrict__ nidx, int n)
{
    const int c = threadIdx.x;
    float w[D0];
#pragma unroll
    for (int i = 0; i < D0; i++) w[i] = W1[c * D0 + i];
    const float bias = b1[c];

    __shared__ float xs[256 * D0];   // 32 KB
    __shared__ int gs[256];

    const int base = blockIdx.x * 256;
    const int cnt = min(256, n - base);

    {   // coalesced vectorized stage of the x tile
        const float4* xv = (const float4*)(x + (size_t)base * D0);
        float4* xsv = (float4*)xs;
        const int nv = cnt * (D0 / 4);
        for (int i = threadIdx.x; i < nv; i += 128) xsv[i] = xv[i];
        for (int i = threadIdx.x; i < cnt; i += 128) gs[i] = nidx[base + i];
    }
    __syncthreads();

    int curg = gs[0];
    float s = 0.f, q = 0.f;
    for (int j = 0; j < cnt; j++) {
        const int g = gs[j];
        if (g != curg) {
            atomicAdd(&g_sum1[curg * D1 + c], s);
            atomicAdd(&g_sq1[curg * D1 + c], q);
            s = 0.f; q = 0.f; curg = g;
        }
        float acc = bias;
        const float4* xr = (const float4*)(xs + j * D0);
#pragma unroll
        for (int i = 0; i < D0 / 4; i++) {
            float4 v = xr[i];
            acc = fmaf(w[4 * i + 0], v.x, acc);
            acc = fmaf(w[4 * i + 1], v.y, acc);
            acc = fmaf(w[4 * i + 2], v.z, acc);
            acc = fmaf(w[4 * i + 3], v.w, acc);
        }
        g_h1[(size_t)(base + j) * D1 + c] = acc;
        s += acc; q = fmaf(acc, acc, q);
    }
    atomicAdd(&g_sum1[curg * D1 + c], s);
    atomicAdd(&g_sq1[curg * D1 + c], q);
}

// ---------------- finalize layer-1 norm: scale/shift per (g,c) --------------
__global__ void k_fin1(const int* __restrict__ nidx, int n,
                       const float* __restrict__ gamma, const float* __restrict__ beta)
{
    __shared__ int lb[NG + 1];
    const int t = threadIdx.x;
    if (t <= NG) {                    // lower_bound(t) in sorted nidx
        const int v = t;
        int lo = 0, hi = n;
        while (lo < hi) { int mid = (lo + hi) >> 1; if (nidx[mid] < v) lo = mid + 1; else hi = mid; }
        lb[t] = lo;
    }
    __syncthreads();
    if (t < NG) g_cntf[t] = (float)max(lb[t + 1] - lb[t], 1);
    for (int idx = t; idx < NG * D1; idx += blockDim.x) {
        const int g = idx >> 7, c = idx & 127;
        const float cf = (float)max(lb[g + 1] - lb[g], 1);
        const float mean = g_sum1[idx] / cf;
        const float var = fmaxf(g_sq1[idx] / cf - mean * mean, 0.f);
        const float sc = gamma[c] * rsqrtf(var + EPSV);
        g_scale1[idx] = sc;
        g_shift1[idx] = fmaf(-mean, sc, beta[c]);
    }
}

// ---------------- k3: a1 = leaky(norm1(h1)); h2 = a1 @ W2^T + b2; stats2 ----
// blockDim = 256 = 16 channel-quads x 16 node-slots. 120 nodes/block, staged 24 at a time.
#define K3_NODES 120
#define K3_STAGE 24
__global__ void __launch_bounds__(256) k3(
    const float* __restrict__ W2, const float* __restrict__ b2,
    const int* __restrict__ nidx, int n)
{
    __shared__ float w2s[D1 * D2];        // transposed: w2s[k*64 + c], 32 KB
    __shared__ float a1s[K3_STAGE * D1];  // 12 KB staged activations
    __shared__ int gs[K3_NODES];

    const int t = threadIdx.x;
    for (int i = t; i < D1 * D2; i += 256) {
        const int c = i >> 7;        // W2 is [64][128] row-major
        const int k = i & 127;
        w2s[k * D2 + c] = W2[i];
    }
    const int base = blockIdx.x * K3_NODES;
    const int cnt = min(K3_NODES, n - base);
    for (int i = t; i < cnt; i += 256) gs[i] = nidx[base + i];

    const int c0 = (t & 15) << 2;    // channel quad base
    const int sl = t >> 4;           // node slot 0..15
    const float bb0 = b2[c0], bb1 = b2[c0 + 1], bb2 = b2[c0 + 2], bb3 = b2[c0 + 3];
    float s0 = 0, s1 = 0, s2 = 0, s3 = 0, q0 = 0, q1 = 0, q2 = 0, q3 = 0;
    __syncthreads();
    int curg = gs[0];

    for (int st = 0; st < cnt; st += K3_STAGE) {
        const int m = min(K3_STAGE, cnt - st);
        __syncthreads();             // previous stage's readers done
        const int nv = (m * D1) >> 2;
        for (int i = t; i < nv; i += 256) {
            const int j = i >> 5;            // node within stage (32 float4 per row)
            const int kq = (i & 31) << 2;
            float4 v = *(const float4*)(g_h1 + (size_t)(base + st + j) * D1 + kq);
            const int g = gs[st + j];
            const float4 sc = *(const float4*)(g_scale1 + g * D1 + kq);
            const float4 sh = *(const float4*)(g_shift1 + g * D1 + kq);
            float4 r;
            r.x = fmaf(v.x, sc.x, sh.x); r.x = r.x >= 0.f ? r.x : r.x * NEG_SLOPE;
            r.y = fmaf(v.y, sc.y, sh.y); r.y = r.y >= 0.f ? r.y : r.y * NEG_SLOPE;
            r.z = fmaf(v.z, sc.z, sh.z); r.z = r.z >= 0.f ? r.z : r.z * NEG_SLOPE;
            r.w = fmaf(v.w, sc.w, sh.w); r.w = r.w >= 0.f ? r.w : r.w * NEG_SLOPE;
            *(float4*)(a1s + j * D1 + kq) = r;
        }
        __syncthreads();

        for (int jj = sl; jj < m; jj += 16) {
            const int g = gs[st + jj];
            if (g != curg) {
                atomicAdd(&g_sum2[curg * D2 + c0 + 0], s0);
                atomicAdd(&g_sum2[curg * D2 + c0 + 1], s1);
                atomicAdd(&g_sum2[curg * D2 + c0 + 2], s2);
                atomicAdd(&g_sum2[curg * D2 + c0 + 3], s3);
                atomicAdd(&g_sq2[curg * D2 + c0 + 0], q0);
                atomicAdd(&g_sq2[curg * D2 + c0 + 1], q1);
                atomicAdd(&g_sq2[curg * D2 + c0 + 2], q2);
                atomicAdd(&g_sq2[curg * D2 + c0 + 3], q3);
                s0 = s1 = s2 = s3 = q0 = q1 = q2 = q3 = 0.f;
                curg = g;
            }
            float a0 = bb0, a1 = bb1, a2 = bb2, a3 = bb3;
            const float* ar = a1s + jj * D1;
#pragma unroll 8
            for (int k = 0; k < D1; k += 4) {
                const float4 av = *(const float4*)(ar + k);
                const float4 wA = *(const float4*)(w2s + (k + 0) * D2 + c0);
                const float4 wB = *(const float4*)(w2s + (k + 1) * D2 + c0);
                const float4 wC = *(const float4*)(w2s + (k + 2) * D2 + c0);
                const float4 wD = *(const float4*)(w2s + (k + 3) * D2 + c0);
                a0 = fmaf(av.x, wA.x, a0); a1 = fmaf(av.x, wA.y, a1);
                a2 = fmaf(av.x, wA.z, a2); a3 = fmaf(av.x, wA.w, a3);
                a0 = fmaf(av.y, wB.x, a0); a1 = fmaf(av.y, wB.y, a1);
                a2 = fmaf(av.y, wB.z, a2); a3 = fmaf(av.y, wB.w, a3);
                a0 = fmaf(av.z, wC.x, a0); a1 = fmaf(av.z, wC.y, a1);
                a2 = fmaf(av.z, wC.z, a2); a3 = fmaf(av.z, wC.w, a3);
                a0 = fmaf(av.w, wD.x, a0); a1 = fmaf(av.w, wD.y, a1);
                a2 = fmaf(av.w, wD.z, a2); a3 = fmaf(av.w, wD.w, a3);
            }
            s0 += a0; q0 = fmaf(a0, a0, q0);
            s1 += a1; q1 = fmaf(a1, a1, q1);
            s2 += a2; q2 = fmaf(a2, a2, q2);
            s3 += a3; q3 = fmaf(a3, a3, q3);
            float4 o; o.x = a0; o.y = a1; o.z = a2; o.w = a3;
            *(float4*)(g_h2 + (size_t)(base + st + jj) * D2 + c0) = o;
        }
    }
    atomicAdd(&g_sum2[curg * D2 + c0 + 0], s0);
    atomicAdd(&g_sum2[curg * D2 + c0 + 1], s1);
    atomicAdd(&g_sum2[curg * D2 + c0 + 2], s2);
    atomicAdd(&g_sum2[curg * D2 + c0 + 3], s3);
    atomicAdd(&g_sq2[curg * D2 + c0 + 0], q0);
    atomicAdd(&g_sq2[curg * D2 + c0 + 1], q1);
    atomicAdd(&g_sq2[curg * D2 + c0 + 2], q2);
    atomicAdd(&g_sq2[curg * D2 + c0 + 3], q3);
}

// ---------------- finalize layer-2 norm -------------------------------------
__global__ void k_fin2(const float* __restrict__ gamma, const float* __restrict__ beta) {
    const int t = threadIdx.x;
    for (int idx = t; idx < NG * D2; idx += blockDim.x) {
        const int g = idx >> 6, c = idx & 63;
        const float cf = g_cntf[g];
        const float mean = g_sum2[idx] / cf;
        const float var = fmaxf(g_sq2[idx] / cf - mean * mean, 0.f);
        const float sc = gamma[c] * rsqrtf(var + EPSV);
        g_scale2[idx] = sc;
        g_shift2[idx] = fmaf(-mean, sc, beta[c]);
    }
}

// ---------------- k5: norm2 + leaky + scatter-max into out ------------------
__global__ void k5(const int* __restrict__ nidx, const int* __restrict__ sidx,
                   float* __restrict__ out, int n)
{
    const int idx = blockIdx.x * blockDim.x + threadIdx.x;
    if (idx >= n * D2) return;
    const int node = idx >> 6;
    const int c = idx & 63;
    const int g = __ldg(&nidx[node]);
    float v = fmaf(g_h2[idx], g_scale2[g * D2 + c], g_shift2[g * D2 + c]);
    v = v >= 0.f ? v : v * NEG_SLOPE;
    const int sp = __ldg(&sidx[node]);
    float* addr = out + (size_t)sp * D2 + c;
    // signed/unsigned atomic max trick for IEEE floats (works across sign mix)
    if (v >= 0.f) atomicMax((int*)addr, __float_as_int(v));
    else          atomicMin((unsigned int*)addr, __float_as_uint(v));
}

// ---------------- k6: empty segments (-inf) -> 0 ----------------------------
__global__ void k6(float* __restrict__ out, int out_n) {
    const int i = blockIdx.x * blockDim.x + threadIdx.x;
    if (i < out_n) {
        if (__float_as_uint(out[i]) == 0xFF800000u) out[i] = 0.f;
    }
}

// ---------------- launcher ---------------------------------------------------
extern "C" void kernel_launch(void* const* d_in, const int* in_sizes, int n_in,
                              void* d_out, int out_size)
{
    const float* x     = (const float*)d_in[0];
    const float* W1    = (const float*)d_in[1];
    const float* b1    = (const float*)d_in[2];
    const float* g1    = (const float*)d_in[3];
    const float* beta1 = (const float*)d_in[4];
    const float* W2    = (const float*)d_in[5];
    const float* b2    = (const float*)d_in[6];
    const float* g2    = (const float*)d_in[7];
    const float* beta2 = (const float*)d_in[8];
    const int*   nidx  = (const int*)d_in[9];    // int32 (JAX x64 disabled)
    const int*   sidx  = (const int*)d_in[10];
    float* out = (float*)d_out;

    const int n = in_sizes[0] / D0;

    k_init<<<(out_size + 255) / 256, 256>>>(out, out_size);
    k1<<<(n + 255) / 256, 128>>>(x, W1, b1, nidx, n);
    k_fin1<<<1, 1024>>>(nidx, n, g1, beta1);
    k3<<<(n + K3_NODES - 1) / K3_NODES, 256>>>(W2, b2, nidx, n);
    k_fin2<<<1, 1024>>>(g2, beta2);
    const long long total = (long long)n * D2;
    k5<<<(int)((total + 255) / 256), 256>>>(nidx, sidx, out, n);
    k6<<<(out_size + 255) / 256, 256>>>(out, out_size);
}

// round 3
// speedup vs baseline: 2.1656x; 2.1656x over previous
#include <cuda_runtime.h>
#include <cstdint>
#include <cstddef>

#define D0 32
#define D1 128
#define D2 64
#define NG 16
#define NEG_SLOPE 0.01f
#define EPSV 1e-5f
#define MAXN 1000000

// ---------------- scratch (static device globals; no runtime allocation) ----
__device__ float g_h1[(size_t)MAXN * D1];   // 512 MB: pre-norm layer-1 activations
__device__ float g_h2[(size_t)MAXN * D2];   // 256 MB: pre-norm layer-2 activations
__device__ float g_sum1[NG * D1], g_sq1[NG * D1];
__device__ float g_sum2[NG * D2], g_sq2[NG * D2];
__device__ float g_scale1[NG * D1], g_shift1[NG * D1];
__device__ float g_scale2[NG * D2], g_shift2[NG * D2];
__device__ float g_cntf[NG];

// ---------------- init: out = -inf, stats = 0 -------------------------------
__global__ void k_init(float* __restrict__ out, int out_n) {
    int i = blockIdx.x * blockDim.x + threadIdx.x;
    if (i < out_n) out[i] = __int_as_float(0xFF800000);  // -inf
    if (i < NG * D1) { g_sum1[i] = 0.f; g_sq1[i] = 0.f; }
    if (i < NG * D2) { g_sum2[i] = 0.f; g_sq2[i] = 0.f; }
}

// ---------------- k1: h1 = x @ W1^T + b1, accumulate per-graph stats --------
__global__ void __launch_bounds__(128) k1(
    const float* __restrict__ x, const float* __restrict__ W1,
    const float* __restrict__ b1, const int* __restrict__ nidx, int n)
{
    const int c = threadIdx.x;
    float w[D0];
#pragma unroll
    for (int i = 0; i < D0; i++) w[i] = W1[c * D0 + i];
    const float bias = b1[c];

    __shared__ float xs[256 * D0];   // 32 KB
    __shared__ int gs[256];

    const int base = blockIdx.x * 256;
    const int cnt = min(256, n - base);

    {
        const float4* xv = (const float4*)(x + (size_t)base * D0);
        float4* xsv = (float4*)xs;
        const int nv = cnt * (D0 / 4);
        for (int i = threadIdx.x; i < nv; i += 128) xsv[i] = xv[i];
        for (int i = threadIdx.x; i < cnt; i += 128) gs[i] = nidx[base + i];
    }
    __syncthreads();

    int curg = gs[0];
    float s = 0.f, q = 0.f;
    for (int j = 0; j < cnt; j++) {
        const int g = gs[j];
        if (g != curg) {
            atomicAdd(&g_sum1[curg * D1 + c], s);
            atomicAdd(&g_sq1[curg * D1 + c], q);
            s = 0.f; q = 0.f; curg = g;
        }
        float acc = bias;
        const float4* xr = (const float4*)(xs + j * D0);
#pragma unroll
        for (int i = 0; i < D0 / 4; i++) {
            float4 v = xr[i];
            acc = fmaf(w[4 * i + 0], v.x, acc);
            acc = fmaf(w[4 * i + 1], v.y, acc);
            acc = fmaf(w[4 * i + 2], v.z, acc);
            acc = fmaf(w[4 * i + 3], v.w, acc);
        }
        g_h1[(size_t)(base + j) * D1 + c] = acc;
        s += acc; q = fmaf(acc, acc, q);
    }
    atomicAdd(&g_sum1[curg * D1 + c], s);
    atomicAdd(&g_sq1[curg * D1 + c], q);
}

// ---------------- finalize layer-1 norm -------------------------------------
__global__ void k_fin1(const int* __restrict__ nidx, int n,
                       const float* __restrict__ gamma, const float* __restrict__ beta)
{
    __shared__ int lb[NG + 1];
    const int t = threadIdx.x;
    if (t <= NG) {
        const int v = t;
        int lo = 0, hi = n;
        while (lo < hi) { int mid = (lo + hi) >> 1; if (nidx[mid] < v) lo = mid + 1; else hi = mid; }
        lb[t] = lo;
    }
    __syncthreads();
    if (t < NG) g_cntf[t] = (float)max(lb[t + 1] - lb[t], 1);
    for (int idx = t; idx < NG * D1; idx += blockDim.x) {
        const int g = idx >> 7, c = idx & 127;
        const float cf = (float)max(lb[g + 1] - lb[g], 1);
        const float mean = g_sum1[idx] / cf;
        const float var = fmaxf(g_sq1[idx] / cf - mean * mean, 0.f);
        const float sc = gamma[c] * rsqrtf(var + EPSV);
        g_scale1[idx] = sc;
        g_shift1[idx] = fmaf(-mean, sc, beta[c]);
    }
}

// ---------------- k3 v2: norm1+leaky -> GEMM2 (4x4 reg tiles) + stats2 ------
// 64 nodes/block, 256 threads = 16 cslots x 16 nslots, thread tile 4n x 4c.
// K=128 processed in 2 halves of 64 to fit smem.
#define K3N 64
#define A1S_STRIDE 68   // 64 k + pad, multiple of 4 for float4 alignment
__global__ void __launch_bounds__(256) k3(
    const float* __restrict__ W2, const float* __restrict__ b2,
    const int* __restrict__ nidx, int n)
{
    __shared__ float a1s[K3N * A1S_STRIDE];   // [node][k-half] 17.4 KB
    __shared__ float w2s[64 * 64];            // [k-half][c]    16.4 KB
    __shared__ float sred[NG * D2 * 2];       // stats table     8 KB
    __shared__ int gs[K3N];

    const int t = threadIdx.x;
    const int base = blockIdx.x * K3N;
    const int cnt = min(K3N, n - base);

    for (int i = t; i < NG * D2 * 2; i += 256) sred[i] = 0.f;
    for (int i = t; i < cnt; i += 256) gs[i] = nidx[base + i];

    const int c0 = (t & 15) << 2;
    const int n0 = (t >> 4) << 2;

    float acc[4][4];
#pragma unroll
    for (int i = 0; i < 4; i++)
#pragma unroll
        for (int j = 0; j < 4; j++) acc[i][j] = 0.f;

    for (int half = 0; half < 2; half++) {
        const int kbase = half * 64;
        __syncthreads();   // protect previous half's smem from overwrite

        // stage W2 half: w2s[k][c] = W2[c*128 + kbase + k]
        for (int i = t; i < 64 * 16; i += 256) {
            const int kq = (i >> 6) << 2;      // 0,4,...,60
            const int c = i & 63;
            float4 wv = *(const float4*)(W2 + c * D1 + kbase + kq);
            w2s[(kq + 0) * 64 + c] = wv.x;
            w2s[(kq + 1) * 64 + c] = wv.y;
            w2s[(kq + 2) * 64 + c] = wv.z;
            w2s[(kq + 3) * 64 + c] = wv.w;
        }

        // stage + normalize a1 half: a1s[node][k] (row-major, coalesced gmem)
        for (int i = t; i < K3N * 16; i += 256) {
            const int node = i >> 4;
            const int kq = (i & 15) << 2;
            float4 r;
            if (node < cnt) {
                float4 v = *(const float4*)(g_h1 + (size_t)(base + node) * D1 + kbase + kq);
                const int g = gs[node];
                const float4 sc = *(const float4*)(g_scale1 + g * D1 + kbase + kq);
                const float4 sh = *(const float4*)(g_shift1 + g * D1 + kbase + kq);
                r.x = fmaf(v.x, sc.x, sh.x); r.x = r.x >= 0.f ? r.x : r.x * NEG_SLOPE;
                r.y = fmaf(v.y, sc.y, sh.y); r.y = r.y >= 0.f ? r.y : r.y * NEG_SLOPE;
                r.z = fmaf(v.z, sc.z, sh.z); r.z = r.z >= 0.f ? r.z : r.z * NEG_SLOPE;
                r.w = fmaf(v.w, sc.w, sh.w); r.w = r.w >= 0.f ? r.w : r.w * NEG_SLOPE;
            } else {
                r.x = r.y = r.z = r.w = 0.f;
            }
            *(float4*)(a1s + node * A1S_STRIDE + kq) = r;
        }
        __syncthreads();

        // GEMM over this k-half
#pragma unroll 4
        for (int k = 0; k < 64; k += 4) {
            const float4 w0 = *(const float4*)(w2s + (k + 0) * 64 + c0);
            const float4 w1 = *(const float4*)(w2s + (k + 1) * 64 + c0);
            const float4 w2v = *(const float4*)(w2s + (k + 2) * 64 + c0);
            const float4 w3 = *(const float4*)(w2s + (k + 3) * 64 + c0);
#pragma unroll
            for (int i = 0; i < 4; i++) {
                const float4 av = *(const float4*)(a1s + (n0 + i) * A1S_STRIDE + k);
                acc[i][0] = fmaf(av.x, w0.x, acc[i][0]);
                acc[i][1] = fmaf(av.x, w0.y, acc[i][1]);
                acc[i][2] = fmaf(av.x, w0.z, acc[i][2]);
                acc[i][3] = fmaf(av.x, w0.w, acc[i][3]);
                acc[i][0] = fmaf(av.y, w1.x, acc[i][0]);
                acc[i][1] = fmaf(av.y, w1.y, acc[i][1]);
                acc[i][2] = fmaf(av.y, w1.z, acc[i][2]);
                acc[i][3] = fmaf(av.y, w1.w, acc[i][3]);
                acc[i][0] = fmaf(av.z, w2v.x, acc[i][0]);
                acc[i][1] = fmaf(av.z, w2v.y, acc[i][1]);
                acc[i][2] = fmaf(av.z, w2v.z, acc[i][2]);
                acc[i][3] = fmaf(av.z, w2v.w, acc[i][3]);
                acc[i][0] = fmaf(av.w, w3.x, acc[i][0]);
                acc[i][1] = fmaf(av.w, w3.y, acc[i][1]);
                acc[i][2] = fmaf(av.w, w3.z, acc[i][2]);
                acc[i][3] = fmaf(av.w, w3.w, acc[i][3]);
            }
        }
    }

    // epilogue: bias, write h2, stats into smem table
    const float4 bv = *(const float4*)(b2 + c0);
    float s0 = 0, s1 = 0, s2 = 0, s3 = 0, q0 = 0, q1 = 0, q2 = 0, q3 = 0;
    int curg = (cnt > 0) ? gs[min(n0, cnt - 1)] : 0;
#pragma unroll
    for (int i = 0; i < 4; i++) {
        if (n0 + i < cnt) {
            const int g = gs[n0 + i];
            if (g != curg) {
                atomicAdd(&sred[(curg * D2 + c0 + 0) * 2 + 0], s0);
                atomicAdd(&sred[(curg * D2 + c0 + 1) * 2 + 0], s1);
                atomicAdd(&sred[(curg * D2 + c0 + 2) * 2 + 0], s2);
                atomicAdd(&sred[(curg * D2 + c0 + 3) * 2 + 0], s3);
                atomicAdd(&sred[(curg * D2 + c0 + 0) * 2 + 1], q0);
                atomicAdd(&sred[(curg * D2 + c0 + 1) * 2 + 1], q1);
                atomicAdd(&sred[(curg * D2 + c0 + 2) * 2 + 1], q2);
                atomicAdd(&sred[(curg * D2 + c0 + 3) * 2 + 1], q3);
                s0 = s1 = s2 = s3 = q0 = q1 = q2 = q3 = 0.f;
                curg = g;
            }
            float4 o;
            o.x = acc[i][0] + bv.x;
            o.y = acc[i][1] + bv.y;
            o.z = acc[i][2] + bv.z;
            o.w = acc[i][3] + bv.w;
            *(float4*)(g_h2 + (size_t)(base + n0 + i) * D2 + c0) = o;
            s0 += o.x; q0 = fmaf(o.x, o.x, q0);
            s1 += o.y; q1 = fmaf(o.y, o.y, q1);
            s2 += o.z; q2 = fmaf(o.z, o.z, q2);
            s3 += o.w; q3 = fmaf(o.w, o.w, q3);
        }
    }
    if (cnt > 0 && n0 < cnt) {
        atomicAdd(&sred[(curg * D2 + c0 + 0) * 2 + 0], s0);
        atomicAdd(&sred[(curg * D2 + c0 + 1) * 2 + 0], s1);
        atomicAdd(&sred[(curg * D2 + c0 + 2) * 2 + 0], s2);
        atomicAdd(&sred[(curg * D2 + c0 + 3) * 2 + 0], s3);
        atomicAdd(&sred[(curg * D2 + c0 + 0) * 2 + 1], q0);
        atomicAdd(&sred[(curg * D2 + c0 + 1) * 2 + 1], q1);
        atomicAdd(&sred[(curg * D2 + c0 + 2) * 2 + 1], q2);
        atomicAdd(&sred[(curg * D2 + c0 + 3) * 2 + 1], q3);
    }
    __syncthreads();

    // block flush: only graphs present in this block
    const int gmin = gs[0];
    const int gmax = gs[cnt - 1];
    const int span = gmax - gmin + 1;
    for (int ii = t; ii < span * D2; ii += 256) {
        const int g = gmin + ii / D2;
        const int c = ii % D2;
        const float sv = sred[(g * D2 + c) * 2 + 0];
        const float qv = sred[(g * D2 + c) * 2 + 1];
        if (sv != 0.f || qv != 0.f) {
            atomicAdd(&g_sum2[g * D2 + c], sv);
            atomicAdd(&g_sq2[g * D2 + c], qv);
        }
    }
}

// ---------------- finalize layer-2 norm -------------------------------------
__global__ void k_fin2(const float* __restrict__ gamma, const float* __restrict__ beta) {
    const int t = threadIdx.x;
    for (int idx = t; idx < NG * D2; idx += blockDim.x) {
        const int g = idx >> 6, c = idx & 63;
        const float cf = g_cntf[g];
        const float mean = g_sum2[idx] / cf;
        const float var = fmaxf(g_sq2[idx] / cf - mean * mean, 0.f);
        const float sc = gamma[c] * rsqrtf(var + EPSV);
        g_scale2[idx] = sc;
        g_shift2[idx] = fmaf(-mean, sc, beta[c]);
    }
}

// ---------------- k5: norm2 + leaky + scatter-max (compare-first) -----------
__global__ void k5(const int* __restrict__ nidx, const int* __restrict__ sidx,
                   float* __restrict__ out, int n)
{
    const int idx = blockIdx.x * blockDim.x + threadIdx.x;
    if (idx >= n * D2) return;
    const int node = idx >> 6;
    const int c = idx & 63;
    const int g = __ldg(&nidx[node]);
    float v = fmaf(g_h2[idx], g_scale2[g * D2 + c], g_shift2[g * D2 + c]);
    v = v >= 0.f ? v : v * NEG_SLOPE;
    const int sp = __ldg(&sidx[node]);
    float* addr = out + (size_t)sp * D2 + c;
    const float cur = *addr;            // monotonic max: stale read => extra atomic only
    if (v > cur) {
        if (v >= 0.f) atomicMax((int*)addr, __float_as_int(v));
        else          atomicMin((unsigned int*)addr, __float_as_uint(v));
    }
}

// ---------------- k6: empty segments (-inf) -> 0 ----------------------------
__global__ void k6(float* __restrict__ out, int out_n) {
    const int i = blockIdx.x * blockDim.x + threadIdx.x;
    if (i < out_n) {
        if (__float_as_uint(out[i]) == 0xFF800000u) out[i] = 0.f;
    }
}

// ---------------- launcher ---------------------------------------------------
extern "C" void kernel_launch(void* const* d_in, const int* in_sizes, int n_in,
                              void* d_out, int out_size)
{
    const float* x     = (const float*)d_in[0];
    const float* W1    = (const float*)d_in[1];
    const float* b1    = (const float*)d_in[2];
    const float* g1    = (const float*)d_in[3];
    const float* beta1 = (const float*)d_in[4];
    const float* W2    = (const float*)d_in[5];
    const float* b2    = (const float*)d_in[6];
    const float* g2    = (const float*)d_in[7];
    const float* beta2 = (const float*)d_in[8];
    const int*   nidx  = (const int*)d_in[9];
    const int*   sidx  = (const int*)d_in[10];
    float* out = (float*)d_out;

    const int n = in_sizes[0] / D0;

    k_init<<<(out_size + 255) / 256, 256>>>(out, out_size);
    k1<<<(n + 255) / 256, 128>>>(x, W1, b1, nidx, n);
    k_fin1<<<1, 1024>>>(nidx, n, g1, beta1);
    k3<<<(n + K3N - 1) / K3N, 256>>>(W2, b2, nidx, n);
    k_fin2<<<1, 1024>>>(g2, beta2);
    const long long total = (long long)n * D2;
    k5<<<(int)((total + 255) / 256), 256>>>(nidx, sidx, out, n);
    k6<<<(out_size + 255) / 256, 256>>>(out, out_size);
}

// round 4
// speedup vs baseline: 2.9419x; 1.3585x over previous
#include <cuda_runtime.h>
#include <cstdint>
#include <cstddef>

#define D0 32
#define D1 128
#define D2 64
#define NG 16
#define NEG_SLOPE 0.01f
#define EPSV 1e-5f
#define MAXN 1000000

// ---------------- scratch ----------------------------------------------------
__device__ float g_h1[(size_t)MAXN * D1];
__device__ float g_h2[(size_t)MAXN * D2];
__device__ float g_w2p[16 * 8 * 32 * 2];    // fragment-permuted tf32 W2 (32 KB)
__device__ float g_sum1[NG * D1], g_sq1[NG * D1];
__device__ float g_sum2[NG * D2], g_sq2[NG * D2];
__device__ float g_scale1[NG * D1], g_shift1[NG * D1];
__device__ float g_scale2[NG * D2], g_shift2[NG * D2];
__device__ float g_cntf[NG];

__device__ __forceinline__ uint32_t f2tf32(float v) {
    uint32_t u;
    asm("cvt.rna.tf32.f32 %0, %1;" : "=r"(u) : "f"(v));
    return u;
}

// ---------------- init -------------------------------------------------------
__global__ void k_init(float* __restrict__ out, int out_n) {
    int i = blockIdx.x * blockDim.x + threadIdx.x;
    if (i < out_n) out[i] = __int_as_float(0xFF800000);
    if (i < NG * D1) { g_sum1[i] = 0.f; g_sq1[i] = 0.f; }
    if (i < NG * D2) { g_sum2[i] = 0.f; g_sq2[i] = 0.f; }
}

// ---------------- W2 -> mma fragment layout (tf32) --------------------------
// B frag for (ktile kt, ntile j): element (krow 0..7, ncol 0..7) at
// offset ((kt*8 + j)*32 + ncol*4 + (krow&3))*2 + (krow>>2).
__global__ void k_w2p(const float* __restrict__ W2) {
    const int i = blockIdx.x * blockDim.x + threadIdx.x;
    if (i >= D2 * D1) return;
    const int c = i >> 7;        // n (0..63)
    const int k = i & 127;       // k (0..127)
    const int kt = k >> 3, krow = k & 7;
    const int j = c >> 3, ncol = c & 7;
    const int off = ((kt * 8 + j) * 32 + ncol * 4 + (krow & 3)) * 2 + (krow >> 2);
    g_w2p[off] = __uint_as_float(f2tf32(W2[c * D1 + k]));
}

// ---------------- k1: h1 = x @ W1^T + b1 + stats1 ---------------------------
__global__ void __launch_bounds__(128) k1(
    const float* __restrict__ x, const float* __restrict__ W1,
    const float* __restrict__ b1, const int* __restrict__ nidx, int n)
{
    const int c = threadIdx.x;
    float w[D0];
#pragma unroll
    for (int i = 0; i < D0; i++) w[i] = W1[c * D0 + i];
    const float bias = b1[c];

    __shared__ float xs[256 * D0];
    __shared__ int gs[256];

    const int base = blockIdx.x * 256;
    const int cnt = min(256, n - base);
    {
        const float4* xv = (const float4*)(x + (size_t)base * D0);
        float4* xsv = (float4*)xs;
        const int nv = cnt * (D0 / 4);
        for (int i = threadIdx.x; i < nv; i += 128) xsv[i] = xv[i];
        for (int i = threadIdx.x; i < cnt; i += 128) gs[i] = nidx[base + i];
    }
    __syncthreads();

    int curg = gs[0];
    float s = 0.f, q = 0.f;
    for (int j = 0; j < cnt; j++) {
        const int g = gs[j];
        if (g != curg) {
            atomicAdd(&g_sum1[curg * D1 + c], s);
            atomicAdd(&g_sq1[curg * D1 + c], q);
            s = 0.f; q = 0.f; curg = g;
        }
        float acc = bias;
        const float4* xr = (const float4*)(xs + j * D0);
#pragma unroll
        for (int i = 0; i < D0 / 4; i++) {
            float4 v = xr[i];
            acc = fmaf(w[4 * i + 0], v.x, acc);
            acc = fmaf(w[4 * i + 1], v.y, acc);
            acc = fmaf(w[4 * i + 2], v.z, acc);
            acc = fmaf(w[4 * i + 3], v.w, acc);
        }
        g_h1[(size_t)(base + j) * D1 + c] = acc;
        s += acc; q = fmaf(acc, acc, q);
    }
    atomicAdd(&g_sum1[curg * D1 + c], s);
    atomicAdd(&g_sq1[curg * D1 + c], q);
}

// ---------------- finalize layer-1 norm -------------------------------------
__global__ void k_fin1(const int* __restrict__ nidx, int n,
                       const float* __restrict__ gamma, const float* __restrict__ beta)
{
    __shared__ int lb[NG + 1];
    const int t = threadIdx.x;
    if (t <= NG) {
        int lo = 0, hi = n;
        while (lo < hi) { int mid = (lo + hi) >> 1; if (nidx[mid] < t) lo = mid + 1; else hi = mid; }
        lb[t] = lo;
    }
    __syncthreads();
    if (t < NG) g_cntf[t] = (float)max(lb[t + 1] - lb[t], 1);
    for (int idx = t; idx < NG * D1; idx += blockDim.x) {
        const int g = idx >> 7, c = idx & 127;
        const float cf = (float)max(lb[g + 1] - lb[g], 1);
        const float mean = g_sum1[idx] / cf;
        const float var = fmaxf(g_sq1[idx] / cf - mean * mean, 0.f);
        const float sc = gamma[c] * rsqrtf(var + EPSV);
        g_scale1[idx] = sc;
        g_shift1[idx] = fmaf(-mean, sc, beta[c]);
    }
}

// ---------------- k3 mma: norm1+leaky -> tf32 GEMM2 + stats2 ----------------
// 128 nodes/block, 256 threads (8 warps), warp w owns m-tile w (16 nodes) x N=64.
// K=128 in 2 halves. A staged fragment-permuted; B pre-permuted (g_w2p).
#define MBLK 128
#define FRS 132                    // fragment-block stride (words), 132%32=4
#define APERM_WORDS (64 * FRS)     // 8 mtiles * 8 ktiles
#define BPERM_WORDS 4096           // per half: 8 kt * 8 nt * 64
#define SRG 4                      // graphs tracked in smem stats

__global__ void __launch_bounds__(256) k3(
    const float* __restrict__ b2, const int* __restrict__ nidx, int n)
{
    extern __shared__ float sm[];
    float* aperm = sm;                          // 33792 B
    float* bperm = aperm + APERM_WORDS;         // 16384 B
    float* sred  = bperm + BPERM_WORDS;         // SRG*64*2 floats
    int*   gs    = (int*)(sred + SRG * D2 * 2); // 128 ints

    const int t = threadIdx.x;
    const int base = blockIdx.x * MBLK;
    const int cnt = min(MBLK, n - base);
    const int w = t >> 5;
    const int lane = t & 31;

    for (int i = t; i < SRG * D2 * 2; i += 256) sred[i] = 0.f;
    for (int i = t; i < MBLK; i += 256) gs[i] = (i < cnt) ? nidx[base + i] : nidx[base + cnt - 1];
    __syncthreads();
    const int gmin = gs[0];

    float acc[8][4];
#pragma unroll
    for (int j = 0; j < 8; j++)
#pragma unroll
        for (int r = 0; r < 4; r++) acc[j][r] = 0.f;

    for (int half = 0; half < 2; half++) {
        const int kbase = half * 64;
        __syncthreads();

        // stage B half (already fragment-permuted, tf32)
        {
            const float4* src = (const float4*)(g_w2p + half * BPERM_WORDS);
            float4* dst = (float4*)bperm;
            for (int i = t; i < BPERM_WORDS / 4; i += 256) dst[i] = src[i];
        }
        // stage A half: normalize+leaky h1, write fragment-permuted tf32
        for (int i = t; i < MBLK * 16; i += 256) {
            const int node = i >> 4;
            const int kq = (i & 15) << 2;          // 0..60 within half
            float4 r;
            if (node < cnt) {
                float4 v = *(const float4*)(g_h1 + (size_t)(base + node) * D1 + kbase + kq);
                const int g = gs[node];
                const float4 sc = *(const float4*)(g_scale1 + g * D1 + kbase + kq);
                const float4 sh = *(const float4*)(g_shift1 + g * D1 + kbase + kq);
                r.x = fmaf(v.x, sc.x, sh.x); r.x = r.x >= 0.f ? r.x : r.x * NEG_SLOPE;
                r.y = fmaf(v.y, sc.y, sh.y); r.y = r.y >= 0.f ? r.y : r.y * NEG_SLOPE;
                r.z = fmaf(v.z, sc.z, sh.z); r.z = r.z >= 0.f ? r.z : r.z * NEG_SLOPE;
                r.w = fmaf(v.w, sc.w, sh.w); r.w = r.w >= 0.f ? r.w : r.w * NEG_SLOPE;
            } else { r.x = r.y = r.z = r.w = 0.f; }
            const int mt = node >> 4;
            const int kt = kq >> 3;
            const int rl = node & 15;
            const int regb = (rl >> 3) + (((kq & 7) >> 2) << 1);
            const int laneb = (rl & 7) << 2;
            float* fb = aperm + (mt * 8 + kt) * FRS;
            fb[(laneb + 0) * 4 + regb] = __uint_as_float(f2tf32(r.x));
            fb[(laneb + 1) * 4 + regb] = __uint_as_float(f2tf32(r.y));
            fb[(laneb + 2) * 4 + regb] = __uint_as_float(f2tf32(r.z));
            fb[(laneb + 3) * 4 + regb] = __uint_as_float(f2tf32(r.w));
        }
        __syncthreads();

        // mma over this half
#pragma unroll
        for (int kt = 0; kt < 8; kt++) {
            const float4 af = *(const float4*)(aperm + (w * 8 + kt) * FRS + lane * 4);
            const uint32_t a0 = __float_as_uint(af.x), a1 = __float_as_uint(af.y);
            const uint32_t a2 = __float_as_uint(af.z), a3 = __float_as_uint(af.w);
#pragma unroll
            for (int j = 0; j < 8; j++) {
                const float2 bf = *(const float2*)(bperm + ((kt * 8 + j) * 32 + lane) * 2);
                const uint32_t b0 = __float_as_uint(bf.x), b1 = __float_as_uint(bf.y);
                asm volatile(
                    "mma.sync.aligned.m16n8k8.row.col.f32.tf32.tf32.f32 "
                    "{%0,%1,%2,%3}, {%4,%5,%6,%7}, {%8,%9}, {%0,%1,%2,%3};"
                    : "+f"(acc[j][0]), "+f"(acc[j][1]), "+f"(acc[j][2]), "+f"(acc[j][3])
                    : "r"(a0), "r"(a1), "r"(a2), "r"(a3), "r"(b0), "r"(b1));
            }
        }
    }

    // epilogue: bias, write h2, stats
    const int grp = lane >> 2, tig = lane & 3;
    const int l0 = w * 16 + grp;        // local node row
    const int l1 = l0 + 8;
    const bool uniform = (w * 16 + 15 < cnt) && (gs[w * 16] == gs[w * 16 + 15]);

#pragma unroll
    for (int j = 0; j < 8; j++) {
        const int nn = j * 8 + tig * 2;
        const float bx = b2[nn], by = b2[nn + 1];
        float v00 = acc[j][0] + bx, v01 = acc[j][1] + by;
        float v10 = acc[j][2] + bx, v11 = acc[j][3] + by;
        if (l0 < cnt) *(float2*)(g_h2 + (size_t)(base + l0) * D2 + nn) = make_float2(v00, v01);
        if (l1 < cnt) *(float2*)(g_h2 + (size_t)(base + l1) * D2 + nn) = make_float2(v10, v11);

        if (uniform) {
            float s0 = v00 + v10, s1 = v01 + v11;
            float q0 = v00 * v00 + v10 * v10, q1 = v01 * v01 + v11 * v11;
#pragma unroll
            for (int off = 4; off < 32; off <<= 1) {
                s0 += __shfl_xor_sync(0xffffffffu, s0, off);
                s1 += __shfl_xor_sync(0xffffffffu, s1, off);
                q0 += __shfl_xor_sync(0xffffffffu, q0, off);
                q1 += __shfl_xor_sync(0xffffffffu, q1, off);
            }
            if (lane < 4) {
                const int gl = gs[w * 16] - gmin;
                atomicAdd(&sred[(gl * D2 + nn) * 2 + 0], s0);
                atomicAdd(&sred[(gl * D2 + nn) * 2 + 1], q0);
                atomicAdd(&sred[(gl * D2 + nn + 1) * 2 + 0], s1);
                atomicAdd(&sred[(gl * D2 + nn + 1) * 2 + 1], q1);
            }
        } else {
            if (l0 < cnt) {
                const int gl = gs[l0] - gmin;
                if (gl < SRG) {
                    atomicAdd(&sred[(gl * D2 + nn) * 2 + 0], v00);
                    atomicAdd(&sred[(gl * D2 + nn) * 2 + 1], v00 * v00);
                    atomicAdd(&sred[(gl * D2 + nn + 1) * 2 + 0], v01);
                    atomicAdd(&sred[(gl * D2 + nn + 1) * 2 + 1], v01 * v01);
                } else {
                    const int g = gs[l0];
                    atomicAdd(&g_sum2[g * D2 + nn], v00);
                    atomicAdd(&g_sq2[g * D2 + nn], v00 * v00);
                    atomicAdd(&g_sum2[g * D2 + nn + 1], v01);
                    atomicAdd(&g_sq2[g * D2 + nn + 1], v01 * v01);
                }
            }
            if (l1 < cnt) {
                const int gl = gs[l1] - gmin;
                if (gl < SRG) {
                    atomicAdd(&sred[(gl * D2 + nn) * 2 + 0], v10);
                    atomicAdd(&sred[(gl * D2 + nn) * 2 + 1], v10 * v10);
                    atomicAdd(&sred[(gl * D2 + nn + 1) * 2 + 0], v11);
                    atomicAdd(&sred[(gl * D2 + nn + 1) * 2 + 1], v11 * v11);
                } else {
                    const int g = gs[l1];
                    atomicAdd(&g_sum2[g * D2 + nn], v10);
                    atomicAdd(&g_sq2[g * D2 + nn], v10 * v10);
                    atomicAdd(&g_sum2[g * D2 + nn + 1], v11);
                    atomicAdd(&g_sq2[g * D2 + nn + 1], v11 * v11);
                }
            }
        }
    }
    __syncthreads();

    // flush block stats
    const int span = min(gs[cnt - 1] - gmin + 1, SRG);
    for (int ii = t; ii < span * D2; ii += 256) {
        const int g = gmin + ii / D2;
        const int c = ii % D2;
        const float sv = sred[(ii % D2 + (ii / D2) * D2) * 2 + 0];
        const float qv = sred[((ii / D2) * D2 + c) * 2 + 1];
        if (sv != 0.f || qv != 0.f) {
            atomicAdd(&g_sum2[g * D2 + c], sv);
            atomicAdd(&g_sq2[g * D2 + c], qv);
        }
    }
}

// ---------------- finalize layer-2 norm -------------------------------------
__global__ void k_fin2(const float* __restrict__ gamma, const float* __restrict__ beta) {
    const int t = threadIdx.x;
    for (int idx = t; idx < NG * D2; idx += blockDim.x) {
        const int g = idx >> 6, c = idx & 63;
        const float cf = g_cntf[g];
        const float mean = g_sum2[idx] / cf;
        const float var = fmaxf(g_sq2[idx] / cf - mean * mean, 0.f);
        const float sc = gamma[c] * rsqrtf(var + EPSV);
        g_scale2[idx] = sc;
        g_shift2[idx] = fmaf(-mean, sc, beta[c]);
    }
}

// ---------------- k5: norm2 + leaky + scatter-max ---------------------------
__global__ void k5(const int* __restrict__ nidx, const int* __restrict__ sidx,
                   float* __restrict__ out, int n)
{
    const int idx = blockIdx.x * blockDim.x + threadIdx.x;
    if (idx >= n * D2) return;
    const int node = idx >> 6;
    const int c = idx & 63;
    const int g = __ldg(&nidx[node]);
    float v = fmaf(g_h2[idx], g_scale2[g * D2 + c], g_shift2[g * D2 + c]);
    v = v >= 0.f ? v : v * NEG_SLOPE;
    const int sp = __ldg(&sidx[node]);
    float* addr = out + (size_t)sp * D2 + c;
    const float cur = *addr;
    if (v > cur) {
        if (v >= 0.f) atomicMax((int*)addr, __float_as_int(v));
        else          atomicMin((unsigned int*)addr, __float_as_uint(v));
    }
}

// ---------------- k6: -inf -> 0 ---------------------------------------------
__global__ void k6(float* __restrict__ out, int out_n) {
    const int i = blockIdx.x * blockDim.x + threadIdx.x;
    if (i < out_n) {
        if (__float_as_uint(out[i]) == 0xFF800000u) out[i] = 0.f;
    }
}

// ---------------- launcher ---------------------------------------------------
extern "C" void kernel_launch(void* const* d_in, const int* in_sizes, int n_in,
                              void* d_out, int out_size)
{
    const float* x     = (const float*)d_in[0];
    const float* W1    = (const float*)d_in[1];
    const float* b1    = (const float*)d_in[2];
    const float* g1    = (const float*)d_in[3];
    const float* beta1 = (const float*)d_in[4];
    const float* W2    = (const float*)d_in[5];
    const float* b2    = (const float*)d_in[6];
    const float* g2    = (const float*)d_in[7];
    const float* beta2 = (const float*)d_in[8];
    const int*   nidx  = (const int*)d_in[9];
    const int*   sidx  = (const int*)d_in[10];
    float* out = (float*)d_out;

    const int n = in_sizes[0] / D0;
    const int smem_k3 = (APERM_WORDS + BPERM_WORDS + SRG * D2 * 2) * 4 + MBLK * 4;
    static int attr_set = 0;
    if (!attr_set) {
        cudaFuncSetAttribute(k3, cudaFuncAttributeMaxDynamicSharedMemorySize, smem_k3);
        attr_set = 1;
    }

    k_init<<<(out_size + 255) / 256, 256>>>(out, out_size);
    k_w2p<<<(D1 * D2 + 255) / 256, 256>>>(W2);
    k1<<<(n + 255) / 256, 128>>>(x, W1, b1, nidx, n);
    k_fin1<<<1, 1024>>>(nidx, n, g1, beta1);
    k3<<<(n + MBLK - 1) / MBLK, 256, smem_k3>>>(b2, nidx, n);
    k_fin2<<<1, 1024>>>(g2, beta2);
    const long long total = (long long)n * D2;
    k5<<<(int)((total + 255) / 256), 256>>>(nidx, sidx, out, n);
    k6<<<(out_size + 255) / 256, 256>>>(out, out_size);
}

// round 7
// speedup vs baseline: 3.1538x; 1.0721x over previous
#include <cuda_runtime.h>
#include <cuda_fp16.h>
#include <cstdint>
#include <cstddef>

#define D0 32
#define D1 128
#define D2 64
#define NG 16
#define NEG_SLOPE 0.01f
#define EPSV 1e-5f
#define MAXN 1000000

// ---------------- scratch ----------------------------------------------------
__device__ __half g_h1h[(size_t)MAXN * D1];  // 256 MB fp16 pre-norm layer-1
__device__ __half g_h2h[(size_t)MAXN * D2];  // 128 MB fp16 pre-norm layer-2
__device__ float g_w2p[16 * 8 * 32 * 2];     // fragment-permuted tf32 W2
__device__ float g_sum1[NG * D1], g_sq1[NG * D1];
__device__ float g_sum2[NG * D2], g_sq2[NG * D2];
__device__ float g_scale1[NG * D1], g_shift1[NG * D1];
__device__ float g_scale2[NG * D2], g_shift2[NG * D2];
__device__ float g_cntf[NG];

__device__ __forceinline__ uint32_t f2tf32(float v) {
    uint32_t u;
    asm("cvt.rna.tf32.f32 %0, %1;" : "=r"(u) : "f"(v));
    return u;
}

// ---------------- init -------------------------------------------------------
__global__ void k_init(float* __restrict__ out, int out_n) {
    int i = blockIdx.x * blockDim.x + threadIdx.x;
    if (i < out_n) out[i] = __int_as_float(0xFF800000);
    if (i < NG * D1) { g_sum1[i] = 0.f; g_sq1[i] = 0.f; }
    if (i < NG * D2) { g_sum2[i] = 0.f; g_sq2[i] = 0.f; }
}

// ---------------- W2 -> mma fragment layout (tf32) --------------------------
__global__ void k_w2p(const float* __restrict__ W2) {
    const int i = blockIdx.x * blockDim.x + threadIdx.x;
    if (i >= D2 * D1) return;
    const int c = i >> 7;
    const int k = i & 127;
    const int kt = k >> 3, krow = k & 7;
    const int j = c >> 3, ncol = c & 7;
    const int off = ((kt * 8 + j) * 32 + ncol * 4 + (krow & 3)) * 2 + (krow >> 2);
    g_w2p[off] = __uint_as_float(f2tf32(W2[c * D1 + k]));
}

// ---------------- k1: h1 = x @ W1^T + b1 (fp16 store) + stats1 --------------
__global__ void __launch_bounds__(128) k1(
    const float* __restrict__ x, const float* __restrict__ W1,
    const float* __restrict__ b1, const int* __restrict__ nidx, int n)
{
    const int c = threadIdx.x;
    float w[D0];
#pragma unroll
    for (int i = 0; i < D0; i++) w[i] = W1[c * D0 + i];
    const float bias = b1[c];

    __shared__ float xs[256 * D0];
    __shared__ int gs[256];

    const int base = blockIdx.x * 256;
    const int cnt = min(256, n - base);
    {
        const float4* xv = (const float4*)(x + (size_t)base * D0);
        float4* xsv = (float4*)xs;
        const int nv = cnt * (D0 / 4);
        for (int i = threadIdx.x; i < nv; i += 128) xsv[i] = xv[i];
        for (int i = threadIdx.x; i < cnt; i += 128) gs[i] = nidx[base + i];
    }
    __syncthreads();

    int curg = gs[0];
    float s = 0.f, q = 0.f;
    for (int j = 0; j < cnt; j++) {
        const int g = gs[j];
        if (g != curg) {
            atomicAdd(&g_sum1[curg * D1 + c], s);
            atomicAdd(&g_sq1[curg * D1 + c], q);
            s = 0.f; q = 0.f; curg = g;
        }
        float acc = bias;
        const float4* xr = (const float4*)(xs + j * D0);
#pragma unroll
        for (int i = 0; i < D0 / 4; i++) {
            float4 v = xr[i];
            acc = fmaf(w[4 * i + 0], v.x, acc);
            acc = fmaf(w[4 * i + 1], v.y, acc);
            acc = fmaf(w[4 * i + 2], v.z, acc);
            acc = fmaf(w[4 * i + 3], v.w, acc);
        }
        const __half h = __float2half(acc);
        g_h1h[(size_t)(base + j) * D1 + c] = h;
        const float ar = __half2float(h);       // stats on the value we stored
        s += ar; q = fmaf(ar, ar, q);
    }
    atomicAdd(&g_sum1[curg * D1 + c], s);
    atomicAdd(&g_sq1[curg * D1 + c], q);
}

// ---------------- finalize layer-1 norm -------------------------------------
__global__ void k_fin1(const int* __restrict__ nidx, int n,
                       const float* __restrict__ gamma, const float* __restrict__ beta)
{
    __shared__ int lb[NG + 1];
    const int t = threadIdx.x;
    if (t <= NG) {
        int lo = 0, hi = n;
        while (lo < hi) { int mid = (lo + hi) >> 1; if (nidx[mid] < t) lo = mid + 1; else hi = mid; }
        lb[t] = lo;
    }
    __syncthreads();
    if (t < NG) g_cntf[t] = (float)max(lb[t + 1] - lb[t], 1);
    for (int idx = t; idx < NG * D1; idx += blockDim.x) {
        const int g = idx >> 7, c = idx & 127;
        const float cf = (float)max(lb[g + 1] - lb[g], 1);
        const float mean = g_sum1[idx] / cf;
        const float var = fmaxf(g_sq1[idx] / cf - mean * mean, 0.f);
        const float sc = gamma[c] * rsqrtf(var + EPSV);
        g_scale1[idx] = sc;
        g_shift1[idx] = fmaf(-mean, sc, beta[c]);
    }
}

// ---------------- k3 mma: norm1+leaky -> tf32 GEMM2 + stats2 ----------------
#define MBLK 128
#define FRS 132
#define APERM_WORDS (64 * FRS)
#define BPERM_WORDS 4096
#define SRG 4

__global__ void __launch_bounds__(256) k3(
    const float* __restrict__ b2, const int* __restrict__ nidx, int n)
{
    extern __shared__ float sm[];
    float* aperm = sm;
    float* bperm = aperm + APERM_WORDS;
    float* sred  = bperm + BPERM_WORDS;
    int*   gs    = (int*)(sred + SRG * D2 * 2);

    const int t = threadIdx.x;
    const int base = blockIdx.x * MBLK;
    const int cnt = min(MBLK, n - base);
    const int w = t >> 5;
    const int lane = t & 31;

    for (int i = t; i < SRG * D2 * 2; i += 256) sred[i] = 0.f;
    for (int i = t; i < MBLK; i += 256) gs[i] = (i < cnt) ? nidx[base + i] : nidx[base + cnt - 1];
    __syncthreads();
    const int gmin = gs[0];

    float acc[8][4];
#pragma unroll
    for (int j = 0; j < 8; j++)
#pragma unroll
        for (int r = 0; r < 4; r++) acc[j][r] = 0.f;

    for (int half = 0; half < 2; half++) {
        const int kbase = half * 64;
        __syncthreads();

        {   // stage B half
            const float4* src = (const float4*)(g_w2p + half * BPERM_WORDS);
            float4* dst = (float4*)bperm;
            for (int i = t; i < BPERM_WORDS / 4; i += 256) dst[i] = src[i];
        }
        // stage A half from fp16 h1: 8 k-values per iter (one float4 = 8 halves)
        for (int i = t; i < MBLK * 8; i += 256) {
            const int node = i >> 3;
            const int kq = (i & 7) << 3;        // 0..56, 8-aligned
            float vv[8];
            if (node < cnt) {
                const float4 hv = *(const float4*)(g_h1h + (size_t)(base + node) * D1 + kbase + kq);
                const __half2* hp = (const __half2*)&hv;
                const int g = gs[node];
                const float* scp = g_scale1 + g * D1 + kbase + kq;
                const float* shp = g_shift1 + g * D1 + kbase + kq;
                const float4 sc0 = *(const float4*)(scp);
                const float4 sc1 = *(const float4*)(scp + 4);
                const float4 sh0 = *(const float4*)(shp);
                const float4 sh1 = *(const float4*)(shp + 4);
                float2 f0 = __half22float2(hp[0]);
                float2 f1 = __half22float2(hp[1]);
                float2 f2 = __half22float2(hp[2]);
                float2 f3 = __half22float2(hp[3]);
                vv[0] = fmaf(f0.x, sc0.x, sh0.x);
                vv[1] = fmaf(f0.y, sc0.y, sh0.y);
                vv[2] = fmaf(f1.x, sc0.z, sh0.z);
                vv[3] = fmaf(f1.y, sc0.w, sh0.w);
                vv[4] = fmaf(f2.x, sc1.x, sh1.x);
                vv[5] = fmaf(f2.y, sc1.y, sh1.y);
                vv[6] = fmaf(f3.x, sc1.z, sh1.z);
                vv[7] = fmaf(f3.y, sc1.w, sh1.w);
#pragma unroll
                for (int u = 0; u < 8; u++) vv[u] = vv[u] >= 0.f ? vv[u] : vv[u] * NEG_SLOPE;
            } else {
#pragma unroll
                for (int u = 0; u < 8; u++) vv[u] = 0.f;
            }
            const int mt = node >> 4;
            const int kt = kq >> 3;
            const int rl = node & 15;
            const int laneb = (rl & 7) << 2;
            const int regb0 = (rl >> 3);
            const int regb1 = regb0 + 2;
            float* fb = aperm + (mt * 8 + kt) * FRS;
            fb[(laneb + 0) * 4 + regb0] = __uint_as_float(f2tf32(vv[0]));
            fb[(laneb + 1) * 4 + regb0] = __uint_as_float(f2tf32(vv[1]));
            fb[(laneb + 2) * 4 + regb0] = __uint_as_float(f2tf32(vv[2]));
            fb[(laneb + 3) * 4 + regb0] = __uint_as_float(f2tf32(vv[3]));
            fb[(laneb + 0) * 4 + regb1] = __uint_as_float(f2tf32(vv[4]));
            fb[(laneb + 1) * 4 + regb1] = __uint_as_float(f2tf32(vv[5]));
            fb[(laneb + 2) * 4 + regb1] = __uint_as_float(f2tf32(vv[6]));
            fb[(laneb + 3) * 4 + regb1] = __uint_as_float(f2tf32(vv[7]));
        }
        __syncthreads();

#pragma unroll
        for (int kt = 0; kt < 8; kt++) {
            const float4 af = *(const float4*)(aperm + (w * 8 + kt) * FRS + lane * 4);
            const uint32_t a0 = __float_as_uint(af.x), a1 = __float_as_uint(af.y);
            const uint32_t a2 = __float_as_uint(af.z), a3 = __float_as_uint(af.w);
#pragma unroll
            for (int j = 0; j < 8; j++) {
                const float2 bf = *(const float2*)(bperm + ((kt * 8 + j) * 32 + lane) * 2);
                const uint32_t b0 = __float_as_uint(bf.x), b1 = __float_as_uint(bf.y);
                asm volatile(
                    "mma.sync.aligned.m16n8k8.row.col.f32.tf32.tf32.f32 "
                    "{%0,%1,%2,%3}, {%4,%5,%6,%7}, {%8,%9}, {%0,%1,%2,%3};"
                    : "+f"(acc[j][0]), "+f"(acc[j][1]), "+f"(acc[j][2]), "+f"(acc[j][3])
                    : "r"(a0), "r"(a1), "r"(a2), "r"(a3), "r"(b0), "r"(b1));
            }
        }
    }

    // epilogue: bias, fp16 h2 store, stats on rounded values
    const int grp = lane >> 2, tig = lane & 3;
    const int l0 = w * 16 + grp;
    const int l1 = l0 + 8;
    const bool uniform = (w * 16 + 15 < cnt) && (gs[w * 16] == gs[w * 16 + 15]);

#pragma unroll
    for (int j = 0; j < 8; j++) {
        const int nn = j * 8 + tig * 2;
        const float bx = b2[nn], by = b2[nn + 1];
        const __half2 p0 = __floats2half2_rn(acc[j][0] + bx, acc[j][1] + by);
        const __half2 p1 = __floats2half2_rn(acc[j][2] + bx, acc[j][3] + by);
        const float2 r0 = __half22float2(p0);
        const float2 r1 = __half22float2(p1);
        if (l0 < cnt) *(__half2*)(g_h2h + (size_t)(base + l0) * D2 + nn) = p0;
        if (l1 < cnt) *(__half2*)(g_h2h + (size_t)(base + l1) * D2 + nn) = p1;

        if (uniform) {
            float s0 = r0.x + r1.x, s1 = r0.y + r1.y;
            float q0 = r0.x * r0.x + r1.x * r1.x, q1 = r0.y * r0.y + r1.y * r1.y;
#pragma unroll
            for (int off = 4; off < 32; off <<= 1) {
                s0 += __shfl_xor_sync(0xffffffffu, s0, off);
                s1 += __shfl_xor_sync(0xffffffffu, s1, off);
                q0 += __shfl_xor_sync(0xffffffffu, q0, off);
                q1 += __shfl_xor_sync(0xffffffffu, q1, off);
            }
            if (lane < 4) {
                const int gl = gs[w * 16] - gmin;
                atomicAdd(&sred[(gl * D2 + nn) * 2 + 0], s0);
                atomicAdd(&sred[(gl * D2 + nn) * 2 + 1], q0);
                atomicAdd(&sred[(gl * D2 + nn + 1) * 2 + 0], s1);
                atomicAdd(&sred[(gl * D2 + nn + 1) * 2 + 1], q1);
            }
        } else {
            if (l0 < cnt) {
                const int gl = gs[l0] - gmin;
                if (gl < SRG) {
                    atomicAdd(&sred[(gl * D2 + nn) * 2 + 0], r0.x);
                    atomicAdd(&sred[(gl * D2 + nn) * 2 + 1], r0.x * r0.x);
                    atomicAdd(&sred[(gl * D2 + nn + 1) * 2 + 0], r0.y);
                    atomicAdd(&sred[(gl * D2 + nn + 1) * 2 + 1], r0.y * r0.y);
                } else {
                    const int g = gs[l0];
                    atomicAdd(&g_sum2[g * D2 + nn], r0.x);
                    atomicAdd(&g_sq2[g * D2 + nn], r0.x * r0.x);
                    atomicAdd(&g_sum2[g * D2 + nn + 1], r0.y);
                    atomicAdd(&g_sq2[g * D2 + nn + 1], r0.y * r0.y);
                }
            }
            if (l1 < cnt) {
                const int gl = gs[l1] - gmin;
                if (gl < SRG) {
                    atomicAdd(&sred[(gl * D2 + nn) * 2 + 0], r1.x);
                    atomicAdd(&sred[(gl * D2 + nn) * 2 + 1], r1.x * r1.x);
                    atomicAdd(&sred[(gl * D2 + nn + 1) * 2 + 0], r1.y);
                    atomicAdd(&sred[(gl * D2 + nn + 1) * 2 + 1], r1.y * r1.y);
                } else {
                    const int g = gs[l1];
                    atomicAdd(&g_sum2[g * D2 + nn], r1.x);
                    atomicAdd(&g_sq2[g * D2 + nn], r1.x * r1.x);
                    atomicAdd(&g_sum2[g * D2 + nn + 1], r1.y);
                    atomicAdd(&g_sq2[g * D2 + nn + 1], r1.y * r1.y);
                }
            }
        }
    }
    __syncthreads();

    const int span = min(gs[cnt - 1] - gmin + 1, SRG);
    for (int ii = t; ii < span * D2; ii += 256) {
        const int g = gmin + ii / D2;
        const int c = ii % D2;
        const float sv = sred[((ii / D2) * D2 + c) * 2 + 0];
        const float qv = sred[((ii / D2) * D2 + c) * 2 + 1];
        if (sv != 0.f || qv != 0.f) {
            atomicAdd(&g_sum2[g * D2 + c], sv);
            atomicAdd(&g_sq2[g * D2 + c], qv);
        }
    }
}

// ---------------- finalize layer-2 norm -------------------------------------
__global__ void k_fin2(const float* __restrict__ gamma, const float* __restrict__ beta) {
    const int t = threadIdx.x;
    for (int idx = t; idx < NG * D2; idx += blockDim.x) {
        const int g = idx >> 6, c = idx & 63;
        const float cf = g_cntf[g];
        const float mean = g_sum2[idx] / cf;
        const float var = fmaxf(g_sq2[idx] / cf - mean * mean, 0.f);
        const float sc = gamma[c] * rsqrtf(var + EPSV);
        g_scale2[idx] = sc;
        g_shift2[idx] = fmaf(-mean, sc, beta[c]);
    }
}

// ---------------- k5: norm2 + leaky + scatter-max (2 ch / thread) -----------
__global__ void k5(const int* __restrict__ nidx, const int* __restrict__ sidx,
                   float* __restrict__ out, int n)
{
    const int idx = blockIdx.x * blockDim.x + threadIdx.x;
    if (idx >= n * 32) return;
    const int node = idx >> 5;
    const int c = (idx & 31) << 1;
    const int g = __ldg(&nidx[node]);
    const __half2 h = *(const __half2*)(g_h2h + (size_t)node * D2 + c);
    const float2 f = __half22float2(h);
    float v0 = fmaf(f.x, g_scale2[g * D2 + c], g_shift2[g * D2 + c]);
    float v1 = fmaf(f.y, g_scale2[g * D2 + c + 1], g_shift2[g * D2 + c + 1]);
    v0 = v0 >= 0.f ? v0 : v0 * NEG_SLOPE;
    v1 = v1 >= 0.f ? v1 : v1 * NEG_SLOPE;
    const int sp = __ldg(&sidx[node]);
    float* a0 = out + (size_t)sp * D2 + c;
    float* a1 = a0 + 1;
    if (v0 > *a0) {
        if (v0 >= 0.f) atomicMax((int*)a0, __float_as_int(v0));
        else           atomicMin((unsigned int*)a0, __float_as_uint(v0));
    }
    if (v1 > *a1) {
        if (v1 >= 0.f) atomicMax((int*)a1, __float_as_int(v1));
        else           atomicMin((unsigned int*)a1, __float_as_uint(v1));
    }
}

// ---------------- k6: -inf -> 0 ---------------------------------------------
__global__ void k6(float* __restrict__ out, int out_n) {
    const int i = blockIdx.x * blockDim.x + threadIdx.x;
    if (i < out_n) {
        if (__float_as_uint(out[i]) == 0xFF800000u) out[i] = 0.f;
    }
}

// ---------------- launcher ---------------------------------------------------
extern "C" void kernel_launch(void* const* d_in, const int* in_sizes, int n_in,
                              void* d_out, int out_size)
{
    const float* x     = (const float*)d_in[0];
    const float* W1    = (const float*)d_in[1];
    const float* b1    = (const float*)d_in[2];
    const float* g1    = (const float*)d_in[3];
    const float* beta1 = (const float*)d_in[4];
    const float* W2    = (const float*)d_in[5];
    const float* b2    = (const float*)d_in[6];
    const float* g2    = (const float*)d_in[7];
    const float* beta2 = (const float*)d_in[8];
    const int*   nidx  = (const int*)d_in[9];
    const int*   sidx  = (const int*)d_in[10];
    float* out = (float*)d_out;

    const int n = in_sizes[0] / D0;
    const int smem_k3 = (APERM_WORDS + BPERM_WORDS + SRG * D2 * 2) * 4 + MBLK * 4;
    static int attr_set = 0;
    if (!attr_set) {
        cudaFuncSetAttribute(k3, cudaFuncAttributeMaxDynamicSharedMemorySize, smem_k3);
        attr_set = 1;
    }

    k_init<<<(out_size + 255) / 256, 256>>>(out, out_size);
    k_w2p<<<(D1 * D2 + 255) / 256, 256>>>(W2);
    k1<<<(n + 255) / 256, 128>>>(x, W1, b1, nidx, n);
    k_fin1<<<1, 1024>>>(nidx, n, g1, beta1);
    k3<<<(n + MBLK - 1) / MBLK, 256, smem_k3>>>(b2, nidx, n);
    k_fin2<<<1, 1024>>>(g2, beta2);
    const long long total = (long long)n * 32;
    k5<<<(int)((total + 255) / 256), 256>>>(nidx, sidx, out, n);
    k6<<<(out_size + 255) / 256, 256>>>(out, out_size);
}